// round 9
// baseline (speedup 1.0000x reference)
#include <cuda_runtime.h>
#include <math.h>
#include <stdint.h>

// ---------------- problem constants ----------------
#define B_   2
#define NQ   2048
#define NKV  2048
#define CQ   1024
#define CK   768
#define HH   8
#define DD   64
#define II   (HH*DD)          // 512
#define SCALE 0.125f
#define LOG2E 1.4426950408889634f

// ---------------- scratch (all tf32 bit patterns) ----------------
__device__ uint32_t g_xp [B_*NQ *CQ];    // pcol-packed A
__device__ uint32_t g_cp [B_*NKV*CK];
__device__ uint32_t g_Wqp[CQ*II];        // (k,k+4) pair-row packed B
__device__ uint32_t g_Wkp[CK*II];
__device__ uint32_t g_Wvp[CK*II];
__device__ uint32_t g_Wop[II*CQ];
__device__ uint32_t g_Q [B_*NQ *II];     // pcol-packed, *SCALE*LOG2E
__device__ uint32_t g_K [B_*NKV*II];     // pcol-packed
__device__ uint32_t g_V [B_*NKV*II];     // (kv,kv+4) pair-row packed: [R/2][II][2]
__device__ uint32_t g_AO[B_*NQ *II];     // pcol-packed

// ---------------- helpers ----------------
__device__ __forceinline__ uint32_t f2tf(float f) {
    uint32_t u;
    asm("cvt.rna.tf32.f32 %0, %1;" : "=r"(u) : "f"(f));
    return u;
}
__device__ __forceinline__ float ex2(float x) {
    float y;
    asm("ex2.approx.ftz.f32 %0, %1;" : "=f"(y) : "f"(x));
    return y;
}
__device__ __forceinline__ void mma_hmma(float c[4], const uint32_t a[4], const uint32_t b[2]) {
    asm("mma.sync.aligned.m16n8k8.row.col.f32.tf32.tf32.f32 "
        "{%0,%1,%2,%3},{%4,%5,%6,%7},{%8,%9},{%0,%1,%2,%3};"
        : "+f"(c[0]), "+f"(c[1]), "+f"(c[2]), "+f"(c[3])
        : "r"(a[0]), "r"(a[1]), "r"(a[2]), "r"(a[3]), "r"(b[0]), "r"(b[1]));
}
__device__ __forceinline__ void cp16(void* sptr, const void* gptr) {
    uint32_t sa = (uint32_t)__cvta_generic_to_shared(sptr);
    asm volatile("cp.async.cg.shared.global [%0], [%1], 16;" :: "r"(sa), "l"(gptr));
}
#define CP_COMMIT() asm volatile("cp.async.commit_group;")

__device__ __forceinline__ int pcol(int c) {
    return (c & ~7) | ((c & 3) << 1) | ((c & 7) >> 2);
}

// ============================================================================
// prep kernels
// ============================================================================
__global__ void pack_a(const float4* __restrict__ in, uint32_t* __restrict__ out, int n4) {
    int i = blockIdx.x * blockDim.x + threadIdx.x;
    if (i >= n4) return;
    float4 v = in[i];
    int base = i * 4;
    int grp  = base & ~7;
    int off  = (base & 4) ? 1 : 0;
    out[grp + off + 0] = f2tf(v.x);
    out[grp + off + 2] = f2tf(v.y);
    out[grp + off + 4] = f2tf(v.z);
    out[grp + off + 6] = f2tf(v.w);
}

__global__ void pack_b(const float* __restrict__ in, uint32_t* __restrict__ out, int N) {
    int n  = blockIdx.x * 128 + threadIdx.x;
    int kk = blockIdx.y;
    int s  = kk >> 3;
    int pr = kk & 7;
    int k0 = s * 16 + ((pr >> 2) << 3) + (pr & 3);
    uint2 v = make_uint2(f2tf(in[(size_t)k0 * N + n]),
                         f2tf(in[(size_t)(k0 + 4) * N + n]));
    *(uint2*)&out[((size_t)kk * N + n) * 2] = v;
}

// ============================================================================
// TF32 GEMM (cp.async-fed, 3-stage). CTA 128x128, BK=16, 8 warps.
// mode: 0=Q (tf32, pcol, *SCALE*LOG2E)  1=K (tf32, pcol)
//       2=V (tf32, pair-row packed)      3=f32 out + bias
// ============================================================================
#define AS 24
#define BSs 264
#define STG_A (128*AS)
#define STG_B (8*BSs)
#define STG_W (STG_A + STG_B)
#define GEMM_SMEM (3*STG_W*4)   // 62208 B

__device__ __forceinline__ void gemm_body(const uint32_t* __restrict__ Ag,
                                          const uint32_t* __restrict__ Bp,
                                          const float* __restrict__ bias,
                                          void* __restrict__ Cv,
                                          int K, int Nn, int mode,
                                          uint32_t* sm)
{
    const int t    = threadIdx.x;
    const int lane = t & 31;
    const int w    = t >> 5;
    const int wrow = w >> 2;
    const int wcol = w & 3;
    const int g    = lane >> 2;
    const int tid4 = lane & 3;
    const int bm = blockIdx.y * 128;
    const int bn = blockIdx.x * 128;
    const int NCH = K >> 4;

    auto load = [&](int ch, int st) {
        uint32_t* ab = sm + st * STG_W;
        uint32_t* bb = ab + STG_A;
        const uint32_t* Asrc = Ag + (size_t)bm * K + ch * 16;
        const uint32_t* Bsrc = Bp + ((size_t)(ch * 8) * Nn + bn) * 2;
        #pragma unroll
        for (int j = 0; j < 2; j++) {
            int idx = t + j * 256;
            int r = idx >> 2, ck = idx & 3;
            cp16(&ab[r * AS + ck * 4], Asrc + (size_t)r * K + ck * 4);
        }
        #pragma unroll
        for (int j = 0; j < 2; j++) {
            int idx = t + j * 256;
            int pr = idx >> 6, nc = idx & 63;
            cp16(&bb[pr * BSs + nc * 4], Bsrc + ((size_t)pr * Nn + nc * 2) * 2);
        }
        CP_COMMIT();
    };

    float acc[4][4][4];
    #pragma unroll
    for (int mt = 0; mt < 4; mt++)
        #pragma unroll
        for (int nt = 0; nt < 4; nt++)
            #pragma unroll
            for (int e = 0; e < 4; e++) acc[mt][nt][e] = 0.f;

    load(0, 0);
    load(1, 1);

    for (int ch = 0; ch < NCH; ch++) {
        if (ch + 1 < NCH) asm volatile("cp.async.wait_group 1;" ::: "memory");
        else              asm volatile("cp.async.wait_group 0;" ::: "memory");
        __syncthreads();
        if (ch + 2 < NCH) load(ch + 2, (ch + 2) % 3);

        const uint32_t* Asc = sm + (ch % 3) * STG_W;
        const uint32_t* Bsc = Asc + STG_A;

        #pragma unroll
        for (int ks = 0; ks < 2; ks++) {
            uint32_t af[4][4], bf[4][2];
            #pragma unroll
            for (int mt = 0; mt < 4; mt++) {
                int r = wrow*64 + mt*16 + g;
                uint2 lo = *(const uint2*)&Asc[r*AS + ks*8 + 2*tid4];
                uint2 hi = *(const uint2*)&Asc[(r+8)*AS + ks*8 + 2*tid4];
                af[mt][0] = lo.x; af[mt][1] = hi.x; af[mt][2] = lo.y; af[mt][3] = hi.y;
            }
            #pragma unroll
            for (int nt = 0; nt < 4; nt++) {
                int cidx = wcol*32 + nt*8 + g;
                uint2 bb = *(const uint2*)&Bsc[(ks*4 + tid4)*BSs + 2*cidx];
                bf[nt][0] = bb.x; bf[nt][1] = bb.y;
            }
            #pragma unroll
            for (int mt = 0; mt < 4; mt++)
                #pragma unroll
                for (int nt = 0; nt < 4; nt++)
                    mma_hmma(acc[mt][nt], af[mt], bf[nt]);
        }
    }

    // epilogue
    #pragma unroll
    for (int mt = 0; mt < 4; mt++) {
        int row0 = bm + wrow*64 + mt*16 + g;
        #pragma unroll
        for (int nt = 0; nt < 4; nt++) {
            int col = bn + wcol*32 + nt*8 + 2*tid4;
            if (mode == 3) {
                float* C = (float*)Cv;
                float bx = bias[col], by = bias[col+1];
                *(float2*)&C[(size_t)row0 * Nn + col] =
                    make_float2(acc[mt][nt][0] + bx, acc[mt][nt][1] + by);
                *(float2*)&C[(size_t)(row0 + 8) * Nn + col] =
                    make_float2(acc[mt][nt][2] + bx, acc[mt][nt][3] + by);
            } else if (mode == 2) {
                // V: pair-row pack (kv, kv+4). Exchange with lane^16 (g ^ 4).
                uint32_t a0 = f2tf(acc[mt][nt][0]);
                uint32_t a1 = f2tf(acc[mt][nt][1]);
                uint32_t a2 = f2tf(acc[mt][nt][2]);
                uint32_t a3 = f2tf(acc[mt][nt][3]);
                uint32_t b0 = __shfl_xor_sync(0xffffffffu, a0, 16);
                uint32_t b1 = __shfl_xor_sync(0xffffffffu, a1, 16);
                uint32_t b2 = __shfl_xor_sync(0xffffffffu, a2, 16);
                uint32_t b3 = __shfl_xor_sync(0xffffffffu, a3, 16);
                uint32_t* C = (uint32_t*)Cv;
                if (g < 4) {
                    size_t P = ((size_t)(row0 >> 3)) * 4 + (row0 & 3);
                    *(uint4*)&C[(P * Nn + col) * 2] = make_uint4(a0, b0, a1, b1);
                } else {
                    int r = row0 + 4;   // lower row of the hi-group pair
                    size_t P = ((size_t)(r >> 3)) * 4 + (r & 3);
                    *(uint4*)&C[(P * Nn + col) * 2] = make_uint4(b2, a2, b3, a3);
                }
            } else {
                const float sc = (mode == 0) ? (SCALE * LOG2E) : 1.0f;
                uint32_t* C = (uint32_t*)Cv;
                int c0 = pcol(col), c1 = pcol(col + 1);
                C[(size_t)row0 * Nn + c0]       = f2tf(acc[mt][nt][0] * sc);
                C[(size_t)row0 * Nn + c1]       = f2tf(acc[mt][nt][1] * sc);
                C[(size_t)(row0 + 8) * Nn + c0] = f2tf(acc[mt][nt][2] * sc);
                C[(size_t)(row0 + 8) * Nn + c1] = f2tf(acc[mt][nt][3] * sc);
            }
        }
    }
}

__global__ __launch_bounds__(256, 2) void gemm_proj() {
    extern __shared__ __align__(16) uint32_t sm[];
    const int z = blockIdx.z;
    const uint32_t* A  = (z == 0) ? g_xp  : g_cp;
    const uint32_t* Bp = (z == 0) ? g_Wqp : ((z == 1) ? g_Wkp : g_Wvp);
    uint32_t*       C  = (z == 0) ? g_Q   : ((z == 1) ? g_K   : g_V);
    const int       K  = (z == 0) ? CQ : CK;
    gemm_body(A, Bp, nullptr, C, K, II, z, sm);
}

__global__ __launch_bounds__(256, 2) void gemm_out(const float* __restrict__ bias,
                                                   float* __restrict__ out) {
    extern __shared__ __align__(16) uint32_t sm[];
    gemm_body(g_AO, g_Wop, bias, out, II, CQ, 3, sm);
}

// ============================================================================
// TF32 flash attention. Q pre-scaled by SCALE*LOG2E -> ex2 softmax.
// V pair-row packed -> single LDS.64 per PV B-frag.
// smem: Q[128x72] + 2x K[128x72] + 2x V[64 pair-rows x 144] = 184320 B.
// ============================================================================
#define QS 72
#define VS 144
#define ATT_T_ELEMS (128*QS)     // 9216 (V tile: 64*144 = 9216 too)
#define ATT_SMEM (5*ATT_T_ELEMS*4)

__global__ __launch_bounds__(256, 1) void attn_tf32() {
    extern __shared__ __align__(16) uint32_t smu[];
    uint32_t* Qs  = smu;
    uint32_t* Kb0 = smu + ATT_T_ELEMS;
    uint32_t* Kb1 = smu + 2*ATT_T_ELEMS;
    uint32_t* Vb0 = smu + 3*ATT_T_ELEMS;
    uint32_t* Vb1 = smu + 4*ATT_T_ELEMS;

    const uint32_t* Qg = g_Q;
    const uint32_t* Kg = g_K;
    const uint32_t* Vg = g_V;

    const int t    = threadIdx.x;
    const int lane = t & 31;
    const int w    = t >> 5;
    const int g    = lane >> 2;
    const int tid4 = lane & 3;

    const int bh = blockIdx.y;
    const int b  = bh >> 3;
    const int h  = bh & 7;
    const int q0 = blockIdx.x * 128;

    // Q tile
    #pragma unroll
    for (int j = 0; j < 8; j++) {
        int idx = t + j*256;
        int row = idx >> 4;
        int d   = (idx & 15) * 4;
        cp16(&Qs[row*QS + d], &Qg[(size_t)(b*NQ + q0 + row)*II + h*DD + d]);
    }
    // K/V tile 0
    {
        size_t Pb = ((size_t)(b*NKV)) >> 1;
        #pragma unroll
        for (int j = 0; j < 8; j++) {
            int idx = t + j*256;
            int row = idx >> 4;
            int d   = (idx & 15) * 4;
            cp16(&Kb0[row*QS + d], &Kg[(size_t)(b*NKV + row)*II + h*DD + d]);
            int pr = idx >> 5;
            int cq = idx & 31;
            cp16(&Vb0[pr*VS + cq*4], &Vg[((Pb + pr)*II + h*DD)*2 + cq*4]);
        }
    }
    CP_COMMIT();

    uint32_t qa[8][4];
    float ofrag[8][4];
    #pragma unroll
    for (int dt = 0; dt < 8; dt++)
        #pragma unroll
        for (int e = 0; e < 4; e++) ofrag[dt][e] = 0.f;
    float m0 = -1e30f, m1 = -1e30f, l0 = 0.f, l1 = 0.f;

    const int src0 = (lane & ~3) | (tid4 >> 1);
    const int src1 = src0 + 2;
    const bool oddl = tid4 & 1;

    for (int it = 0; it < NKV/128; it++) {
        const int cur = it & 1;
        uint32_t* Kc = cur ? Kb1 : Kb0;
        uint32_t* Vc = cur ? Vb1 : Vb0;

        if (it + 1 < NKV/128) {
            uint32_t* Kn = cur ? Kb0 : Kb1;
            uint32_t* Vn = cur ? Vb0 : Vb1;
            int kv0n = (it + 1) * 128;
            size_t Pb = ((size_t)(b*NKV + kv0n)) >> 1;
            #pragma unroll
            for (int j = 0; j < 8; j++) {
                int idx = t + j*256;
                int row = idx >> 4;
                int d   = (idx & 15) * 4;
                cp16(&Kn[row*QS + d], &Kg[(size_t)(b*NKV + kv0n + row)*II + h*DD + d]);
                int pr = idx >> 5;
                int cq = idx & 31;
                cp16(&Vn[pr*VS + cq*4], &Vg[((Pb + pr)*II + h*DD)*2 + cq*4]);
            }
            CP_COMMIT();
            asm volatile("cp.async.wait_group 1;" ::: "memory");
        } else {
            asm volatile("cp.async.wait_group 0;" ::: "memory");
        }
        __syncthreads();

        if (it == 0) {
            int r0 = (w*16 + g) * QS;
            int r1 = (w*16 + g + 8) * QS;
            #pragma unroll
            for (int ks = 0; ks < 8; ks++) {
                uint2 lo = *(const uint2*)&Qs[r0 + ks*8 + 2*tid4];
                uint2 hi = *(const uint2*)&Qs[r1 + ks*8 + 2*tid4];
                qa[ks][0] = lo.x; qa[ks][1] = hi.x; qa[ks][2] = lo.y; qa[ks][3] = hi.y;
            }
        }

        // ---- S = Q K^T (log2-scaled) ----
        float sfrag[16][4];
        #pragma unroll
        for (int nt = 0; nt < 16; nt++) {
            sfrag[nt][0]=0.f; sfrag[nt][1]=0.f; sfrag[nt][2]=0.f; sfrag[nt][3]=0.f;
            int krow = (nt*8 + g) * QS;
            #pragma unroll
            for (int ks = 0; ks < 8; ks++) {
                uint2 bb = *(const uint2*)&Kc[krow + ks*8 + 2*tid4];
                uint32_t bf[2] = {bb.x, bb.y};
                mma_hmma(sfrag[nt], qa[ks], bf);
            }
        }

        // ---- online softmax (base-2) ----
        float tm0 = sfrag[0][0], tm1 = sfrag[0][2];
        #pragma unroll
        for (int nt = 0; nt < 16; nt++) {
            tm0 = fmaxf(tm0, fmaxf(sfrag[nt][0], sfrag[nt][1]));
            tm1 = fmaxf(tm1, fmaxf(sfrag[nt][2], sfrag[nt][3]));
        }
        tm0 = fmaxf(tm0, __shfl_xor_sync(0xffffffffu, tm0, 1));
        tm0 = fmaxf(tm0, __shfl_xor_sync(0xffffffffu, tm0, 2));
        tm1 = fmaxf(tm1, __shfl_xor_sync(0xffffffffu, tm1, 1));
        tm1 = fmaxf(tm1, __shfl_xor_sync(0xffffffffu, tm1, 2));
        float mn0 = fmaxf(m0, tm0), mn1 = fmaxf(m1, tm1);
        float al0 = ex2(m0 - mn0), al1 = ex2(m1 - mn1);
        m0 = mn0; m1 = mn1;
        float sum0 = 0.f, sum1 = 0.f;
        #pragma unroll
        for (int nt = 0; nt < 16; nt++) {
            sfrag[nt][0] = ex2(sfrag[nt][0] - mn0);
            sfrag[nt][1] = ex2(sfrag[nt][1] - mn0);
            sfrag[nt][2] = ex2(sfrag[nt][2] - mn1);
            sfrag[nt][3] = ex2(sfrag[nt][3] - mn1);
            sum0 += sfrag[nt][0] + sfrag[nt][1];
            sum1 += sfrag[nt][2] + sfrag[nt][3];
        }
        sum0 += __shfl_xor_sync(0xffffffffu, sum0, 1);
        sum0 += __shfl_xor_sync(0xffffffffu, sum0, 2);
        sum1 += __shfl_xor_sync(0xffffffffu, sum1, 1);
        sum1 += __shfl_xor_sync(0xffffffffu, sum1, 2);
        l0 = l0*al0 + sum0;
        l1 = l1*al1 + sum1;

        #pragma unroll
        for (int dt = 0; dt < 8; dt++) {
            ofrag[dt][0] *= al0; ofrag[dt][1] *= al0;
            ofrag[dt][2] *= al1; ofrag[dt][3] *= al1;
        }

        // ---- O += P @ V (V pair-packed -> LDS.64 B-frags) ----
        #pragma unroll
        for (int ks = 0; ks < 16; ks++) {
            uint32_t p0 = f2tf(sfrag[ks][0]);
            uint32_t p1 = f2tf(sfrag[ks][1]);
            uint32_t p2 = f2tf(sfrag[ks][2]);
            uint32_t p3 = f2tf(sfrag[ks][3]);
            uint32_t x0 = __shfl_sync(0xffffffffu, p0, src0);
            uint32_t y0 = __shfl_sync(0xffffffffu, p1, src0);
            uint32_t x2 = __shfl_sync(0xffffffffu, p0, src1);
            uint32_t y2 = __shfl_sync(0xffffffffu, p1, src1);
            uint32_t x1 = __shfl_sync(0xffffffffu, p2, src0);
            uint32_t y1 = __shfl_sync(0xffffffffu, p3, src0);
            uint32_t x3 = __shfl_sync(0xffffffffu, p2, src1);
            uint32_t y3 = __shfl_sync(0xffffffffu, p3, src1);
            uint32_t af[4];
            af[0] = oddl ? y0 : x0;
            af[1] = oddl ? y1 : x1;
            af[2] = oddl ? y2 : x2;
            af[3] = oddl ? y3 : x3;
            const int vbase = (ks*4 + tid4)*VS;
            #pragma unroll
            for (int dt = 0; dt < 8; dt++) {
                uint2 vv = *(const uint2*)&Vc[vbase + (dt*8 + g)*2];
                uint32_t vb[2] = {vv.x, vv.y};
                mma_hmma(ofrag[dt], af, vb);
            }
        }
        __syncthreads();
    }

    // normalize + store pcol-packed tf32
    float inv0 = 1.0f / l0, inv1 = 1.0f / l1;
    int r0 = b*NQ + q0 + w*16 + g;
    uint32_t* AOu = g_AO;
    #pragma unroll
    for (int dt = 0; dt < 8; dt++) {
        int col = dt*8 + 2*tid4;
        int c0 = pcol(col), c1 = pcol(col + 1);
        size_t ro0 = (size_t)r0*II + h*DD;
        size_t ro1 = (size_t)(r0 + 8)*II + h*DD;
        AOu[ro0 + c0] = f2tf(ofrag[dt][0]*inv0);
        AOu[ro0 + c1] = f2tf(ofrag[dt][1]*inv0);
        AOu[ro1 + c0] = f2tf(ofrag[dt][2]*inv1);
        AOu[ro1 + c1] = f2tf(ofrag[dt][3]*inv1);
    }
}

// ============================================================================
// launch
// ============================================================================
extern "C" void kernel_launch(void* const* d_in, const int* in_sizes, int n_in,
                              void* d_out, int out_size)
{
    const float* x   = (const float*)d_in[0];
    const float* ctx = (const float*)d_in[1];
    const float* Wq  = (const float*)d_in[2];
    const float* Wk  = (const float*)d_in[3];
    const float* Wv  = (const float*)d_in[4];
    const float* Wo  = (const float*)d_in[5];
    const float* bo  = (const float*)d_in[6];
    float* out = (float*)d_out;

    uint32_t *xp, *cp, *Wqp, *Wkp, *Wvp, *Wop;
    cudaGetSymbolAddress((void**)&xp,  g_xp);
    cudaGetSymbolAddress((void**)&cp,  g_cp);
    cudaGetSymbolAddress((void**)&Wqp, g_Wqp);
    cudaGetSymbolAddress((void**)&Wkp, g_Wkp);
    cudaGetSymbolAddress((void**)&Wvp, g_Wvp);
    cudaGetSymbolAddress((void**)&Wop, g_Wop);

    // prep
    pack_a<<<(B_*NQ*CQ/4 + 255)/256, 256>>>((const float4*)x,   xp, B_*NQ*CQ/4);
    pack_a<<<(B_*NKV*CK/4 + 255)/256, 256>>>((const float4*)ctx, cp, B_*NKV*CK/4);
    pack_b<<<dim3(II/128, CQ/2), 128>>>(Wq, Wqp, II);
    pack_b<<<dim3(II/128, CK/2), 128>>>(Wk, Wkp, II);
    pack_b<<<dim3(II/128, CK/2), 128>>>(Wv, Wvp, II);
    pack_b<<<dim3(CQ/128, II/2), 128>>>(Wo, Wop, CQ);

    // projections
    cudaFuncSetAttribute(gemm_proj, cudaFuncAttributeMaxDynamicSharedMemorySize, GEMM_SMEM);
    gemm_proj<<<dim3(II/128, (B_*NQ)/128, 3), 256, GEMM_SMEM>>>();

    // attention
    cudaFuncSetAttribute(attn_tf32, cudaFuncAttributeMaxDynamicSharedMemorySize, ATT_SMEM);
    attn_tf32<<<dim3(NQ/128, B_*HH), 256, ATT_SMEM>>>();

    // output projection + bias
    cudaFuncSetAttribute(gemm_out, cudaFuncAttributeMaxDynamicSharedMemorySize, GEMM_SMEM);
    gemm_out<<<dim3(CQ/128, (B_*NQ)/128), 256, GEMM_SMEM>>>(bo, out);
}

// round 11
// speedup vs baseline: 1.1079x; 1.1079x over previous
#include <cuda_runtime.h>
#include <math.h>
#include <stdint.h>

// ---------------- problem constants ----------------
#define B_   2
#define NQ   2048
#define NKV  2048
#define CQ   1024
#define CK   768
#define HH   8
#define DD   64
#define II   (HH*DD)          // 512
#define SCALE 0.125f
#define LOG2E 1.4426950408889634f

// ---------------- scratch (all tf32 bit patterns) ----------------
__device__ uint32_t g_xp [B_*NQ *CQ];    // pcol-packed A
__device__ uint32_t g_cp [B_*NKV*CK];
__device__ uint32_t g_Wqp[CQ*II];        // (k,k+4) pair-row packed B
__device__ uint32_t g_Wkp[CK*II];
__device__ uint32_t g_Wvp[CK*II];
__device__ uint32_t g_Wop[II*CQ];
__device__ uint32_t g_Q [B_*NQ *II];     // pcol-packed, *SCALE*LOG2E
__device__ uint32_t g_K [B_*NKV*II];     // pcol-packed
__device__ uint32_t g_V [B_*NKV*II];     // (kv,kv+4) pair-row packed: [R/2][II][2]
__device__ uint32_t g_AO[B_*NQ *II];     // pcol-packed

// ---------------- helpers ----------------
__device__ __forceinline__ uint32_t f2tf(float f) {
    uint32_t u;
    asm("cvt.rna.tf32.f32 %0, %1;" : "=r"(u) : "f"(f));
    return u;
}
__device__ __forceinline__ float ex2(float x) {
    float y;
    asm("ex2.approx.ftz.f32 %0, %1;" : "=f"(y) : "f"(x));
    return y;
}
__device__ __forceinline__ void mma_hmma(float c[4], const uint32_t a[4], const uint32_t b[2]) {
    asm("mma.sync.aligned.m16n8k8.row.col.f32.tf32.tf32.f32 "
        "{%0,%1,%2,%3},{%4,%5,%6,%7},{%8,%9},{%0,%1,%2,%3};"
        : "+f"(c[0]), "+f"(c[1]), "+f"(c[2]), "+f"(c[3])
        : "r"(a[0]), "r"(a[1]), "r"(a[2]), "r"(a[3]), "r"(b[0]), "r"(b[1]));
}
__device__ __forceinline__ void cp16(void* sptr, const void* gptr) {
    uint32_t sa = (uint32_t)__cvta_generic_to_shared(sptr);
    asm volatile("cp.async.cg.shared.global [%0], [%1], 16;" :: "r"(sa), "l"(gptr));
}
#define CP_COMMIT() asm volatile("cp.async.commit_group;")

__device__ __forceinline__ int pcol(int c) {
    return (c & ~7) | ((c & 3) << 1) | ((c & 7) >> 2);
}

// ============================================================================
// prep kernels
// ============================================================================
__global__ void pack_a(const float4* __restrict__ in, uint32_t* __restrict__ out, int n4) {
    int i = blockIdx.x * blockDim.x + threadIdx.x;
    if (i >= n4) return;
    float4 v = in[i];
    int base = i * 4;
    int grp  = base & ~7;
    int off  = (base & 4) ? 1 : 0;
    out[grp + off + 0] = f2tf(v.x);
    out[grp + off + 2] = f2tf(v.y);
    out[grp + off + 4] = f2tf(v.z);
    out[grp + off + 6] = f2tf(v.w);
}

__global__ void pack_b(const float* __restrict__ in, uint32_t* __restrict__ out, int N) {
    int n  = blockIdx.x * 128 + threadIdx.x;
    int kk = blockIdx.y;
    int s  = kk >> 3;
    int pr = kk & 7;
    int k0 = s * 16 + ((pr >> 2) << 3) + (pr & 3);
    uint2 v = make_uint2(f2tf(in[(size_t)k0 * N + n]),
                         f2tf(in[(size_t)(k0 + 4) * N + n]));
    *(uint2*)&out[((size_t)kk * N + n) * 2] = v;
}

// ============================================================================
// TF32 GEMM (cp.async-fed, 3-stage). CTA 128x128, BK=16, 8 warps.
// mode: 0=Q (tf32, pcol, *SCALE*LOG2E)  1=K (tf32, pcol)
//       2=V (tf32, pair-row packed)      3=f32 out + bias
// ============================================================================
#define AS 24
#define BSs 264
#define STG_A (128*AS)
#define STG_B (8*BSs)
#define STG_W (STG_A + STG_B)
#define GEMM_SMEM (3*STG_W*4)   // 62208 B

__device__ __forceinline__ void gemm_body(const uint32_t* __restrict__ Ag,
                                          const uint32_t* __restrict__ Bp,
                                          const float* __restrict__ bias,
                                          void* __restrict__ Cv,
                                          int K, int Nn, int mode,
                                          uint32_t* sm)
{
    const int t    = threadIdx.x;
    const int lane = t & 31;
    const int w    = t >> 5;
    const int wrow = w >> 2;
    const int wcol = w & 3;
    const int g    = lane >> 2;
    const int tid4 = lane & 3;
    const int bm = blockIdx.y * 128;
    const int bn = blockIdx.x * 128;
    const int NCH = K >> 4;

    auto load = [&](int ch, int st) {
        uint32_t* ab = sm + st * STG_W;
        uint32_t* bb = ab + STG_A;
        const uint32_t* Asrc = Ag + (size_t)bm * K + ch * 16;
        const uint32_t* Bsrc = Bp + ((size_t)(ch * 8) * Nn + bn) * 2;
        #pragma unroll
        for (int j = 0; j < 2; j++) {
            int idx = t + j * 256;
            int r = idx >> 2, ck = idx & 3;
            cp16(&ab[r * AS + ck * 4], Asrc + (size_t)r * K + ck * 4);
        }
        #pragma unroll
        for (int j = 0; j < 2; j++) {
            int idx = t + j * 256;
            int pr = idx >> 6, nc = idx & 63;
            cp16(&bb[pr * BSs + nc * 4], Bsrc + ((size_t)pr * Nn + nc * 2) * 2);
        }
        CP_COMMIT();
    };

    float acc[4][4][4];
    #pragma unroll
    for (int mt = 0; mt < 4; mt++)
        #pragma unroll
        for (int nt = 0; nt < 4; nt++)
            #pragma unroll
            for (int e = 0; e < 4; e++) acc[mt][nt][e] = 0.f;

    load(0, 0);
    load(1, 1);

    for (int ch = 0; ch < NCH; ch++) {
        if (ch + 1 < NCH) asm volatile("cp.async.wait_group 1;" ::: "memory");
        else              asm volatile("cp.async.wait_group 0;" ::: "memory");
        __syncthreads();
        if (ch + 2 < NCH) load(ch + 2, (ch + 2) % 3);

        const uint32_t* Asc = sm + (ch % 3) * STG_W;
        const uint32_t* Bsc = Asc + STG_A;

        #pragma unroll
        for (int ks = 0; ks < 2; ks++) {
            uint32_t af[4][4], bf[4][2];
            #pragma unroll
            for (int mt = 0; mt < 4; mt++) {
                int r = wrow*64 + mt*16 + g;
                uint2 lo = *(const uint2*)&Asc[r*AS + ks*8 + 2*tid4];
                uint2 hi = *(const uint2*)&Asc[(r+8)*AS + ks*8 + 2*tid4];
                af[mt][0] = lo.x; af[mt][1] = hi.x; af[mt][2] = lo.y; af[mt][3] = hi.y;
            }
            #pragma unroll
            for (int nt = 0; nt < 4; nt++) {
                int cidx = wcol*32 + nt*8 + g;
                uint2 bb = *(const uint2*)&Bsc[(ks*4 + tid4)*BSs + 2*cidx];
                bf[nt][0] = bb.x; bf[nt][1] = bb.y;
            }
            #pragma unroll
            for (int mt = 0; mt < 4; mt++)
                #pragma unroll
                for (int nt = 0; nt < 4; nt++)
                    mma_hmma(acc[mt][nt], af[mt], bf[nt]);
        }
    }

    // epilogue
    #pragma unroll
    for (int mt = 0; mt < 4; mt++) {
        int row0 = bm + wrow*64 + mt*16 + g;
        #pragma unroll
        for (int nt = 0; nt < 4; nt++) {
            int col = bn + wcol*32 + nt*8 + 2*tid4;
            if (mode == 3) {
                float* C = (float*)Cv;
                float bx = bias[col], by = bias[col+1];
                *(float2*)&C[(size_t)row0 * Nn + col] =
                    make_float2(acc[mt][nt][0] + bx, acc[mt][nt][1] + by);
                *(float2*)&C[(size_t)(row0 + 8) * Nn + col] =
                    make_float2(acc[mt][nt][2] + bx, acc[mt][nt][3] + by);
            } else if (mode == 2) {
                // V: pair-row pack (kv, kv+4). Exchange with lane^16 (g ^ 4).
                uint32_t a0 = f2tf(acc[mt][nt][0]);
                uint32_t a1 = f2tf(acc[mt][nt][1]);
                uint32_t a2 = f2tf(acc[mt][nt][2]);
                uint32_t a3 = f2tf(acc[mt][nt][3]);
                uint32_t b0 = __shfl_xor_sync(0xffffffffu, a0, 16);
                uint32_t b1 = __shfl_xor_sync(0xffffffffu, a1, 16);
                uint32_t b2 = __shfl_xor_sync(0xffffffffu, a2, 16);
                uint32_t b3 = __shfl_xor_sync(0xffffffffu, a3, 16);
                uint32_t* C = (uint32_t*)Cv;
                if (g < 4) {
                    size_t P = ((size_t)(row0 >> 3)) * 4 + (row0 & 3);
                    *(uint4*)&C[(P * Nn + col) * 2] = make_uint4(a0, b0, a1, b1);
                } else {
                    int r = row0 + 4;   // lower row of the hi-group pair
                    size_t P = ((size_t)(r >> 3)) * 4 + (r & 3);
                    *(uint4*)&C[(P * Nn + col) * 2] = make_uint4(b2, a2, b3, a3);
                }
            } else {
                const float sc = (mode == 0) ? (SCALE * LOG2E) : 1.0f;
                uint32_t* C = (uint32_t*)Cv;
                int c0 = pcol(col), c1 = pcol(col + 1);
                C[(size_t)row0 * Nn + c0]       = f2tf(acc[mt][nt][0] * sc);
                C[(size_t)row0 * Nn + c1]       = f2tf(acc[mt][nt][1] * sc);
                C[(size_t)(row0 + 8) * Nn + c0] = f2tf(acc[mt][nt][2] * sc);
                C[(size_t)(row0 + 8) * Nn + c1] = f2tf(acc[mt][nt][3] * sc);
            }
        }
    }
}

__global__ __launch_bounds__(256, 2) void gemm_proj() {
    extern __shared__ __align__(16) uint32_t sm[];
    const int z = blockIdx.z;
    const uint32_t* A  = (z == 0) ? g_xp  : g_cp;
    const uint32_t* Bp = (z == 0) ? g_Wqp : ((z == 1) ? g_Wkp : g_Wvp);
    uint32_t*       C  = (z == 0) ? g_Q   : ((z == 1) ? g_K   : g_V);
    const int       K  = (z == 0) ? CQ : CK;
    gemm_body(A, Bp, nullptr, C, K, II, z, sm);
}

__global__ __launch_bounds__(256, 2) void gemm_out(const float* __restrict__ bias,
                                                   float* __restrict__ out) {
    extern __shared__ __align__(16) uint32_t sm[];
    gemm_body(g_AO, g_Wop, bias, out, II, CQ, 3, sm);
}

// ============================================================================
// TF32 flash attention. Q pre-scaled by SCALE*LOG2E -> ex2 softmax.
// V pair-row packed -> single conflict-free LDS.64 per PV B-frag (VS=136:
// 136 mod 32 = 8 -> phase bank = 8*tid4 + 2g, disjoint octets).
// smem: Q[128x72] + 2x K[128x72] + 2x V[64x136] = 180224 B.
// ============================================================================
#define QS 72
#define VS 136
#define ATT_T_ELEMS (128*QS)     // 9216
#define V_T_ELEMS (64*VS)        // 8704
#define ATT_SMEM ((3*ATT_T_ELEMS + 2*V_T_ELEMS)*4)   // 180224 B

__global__ __launch_bounds__(256, 1) void attn_tf32() {
    extern __shared__ __align__(16) uint32_t smu[];
    uint32_t* Qs  = smu;
    uint32_t* Kb0 = smu + ATT_T_ELEMS;
    uint32_t* Kb1 = smu + 2*ATT_T_ELEMS;
    uint32_t* Vb0 = smu + 3*ATT_T_ELEMS;
    uint32_t* Vb1 = Vb0 + V_T_ELEMS;

    const uint32_t* Qg = g_Q;
    const uint32_t* Kg = g_K;
    const uint32_t* Vg = g_V;

    const int t    = threadIdx.x;
    const int lane = t & 31;
    const int w    = t >> 5;
    const int g    = lane >> 2;
    const int tid4 = lane & 3;

    const int bh = blockIdx.y;
    const int b  = bh >> 3;
    const int h  = bh & 7;
    const int q0 = blockIdx.x * 128;

    // Q tile
    #pragma unroll
    for (int j = 0; j < 8; j++) {
        int idx = t + j*256;
        int row = idx >> 4;
        int d   = (idx & 15) * 4;
        cp16(&Qs[row*QS + d], &Qg[(size_t)(b*NQ + q0 + row)*II + h*DD + d]);
    }
    // K/V tile 0
    {
        size_t Pb = ((size_t)(b*NKV)) >> 1;
        #pragma unroll
        for (int j = 0; j < 8; j++) {
            int idx = t + j*256;
            int row = idx >> 4;
            int d   = (idx & 15) * 4;
            cp16(&Kb0[row*QS + d], &Kg[(size_t)(b*NKV + row)*II + h*DD + d]);
            int pr = idx >> 5;
            int cq = idx & 31;
            cp16(&Vb0[pr*VS + cq*4], &Vg[((Pb + pr)*II + h*DD)*2 + cq*4]);
        }
    }
    CP_COMMIT();

    uint32_t qa[8][4];
    float ofrag[8][4];
    #pragma unroll
    for (int dt = 0; dt < 8; dt++)
        #pragma unroll
        for (int e = 0; e < 4; e++) ofrag[dt][e] = 0.f;
    float m0 = -1e30f, m1 = -1e30f, l0 = 0.f, l1 = 0.f;

    const int src0 = (lane & ~3) | (tid4 >> 1);
    const int src1 = src0 + 2;
    const bool oddl = tid4 & 1;

    for (int it = 0; it < NKV/128; it++) {
        const int cur = it & 1;
        uint32_t* Kc = cur ? Kb1 : Kb0;
        uint32_t* Vc = cur ? Vb1 : Vb0;

        if (it + 1 < NKV/128) {
            uint32_t* Kn = cur ? Kb0 : Kb1;
            uint32_t* Vn = cur ? Vb0 : Vb1;
            int kv0n = (it + 1) * 128;
            size_t Pb = ((size_t)(b*NKV + kv0n)) >> 1;
            #pragma unroll
            for (int j = 0; j < 8; j++) {
                int idx = t + j*256;
                int row = idx >> 4;
                int d   = (idx & 15) * 4;
                cp16(&Kn[row*QS + d], &Kg[(size_t)(b*NKV + kv0n + row)*II + h*DD + d]);
                int pr = idx >> 5;
                int cq = idx & 31;
                cp16(&Vn[pr*VS + cq*4], &Vg[((Pb + pr)*II + h*DD)*2 + cq*4]);
            }
            CP_COMMIT();
            asm volatile("cp.async.wait_group 1;" ::: "memory");
        } else {
            asm volatile("cp.async.wait_group 0;" ::: "memory");
        }
        __syncthreads();

        if (it == 0) {
            int r0 = (w*16 + g) * QS;
            int r1 = (w*16 + g + 8) * QS;
            #pragma unroll
            for (int ks = 0; ks < 8; ks++) {
                uint2 lo = *(const uint2*)&Qs[r0 + ks*8 + 2*tid4];
                uint2 hi = *(const uint2*)&Qs[r1 + ks*8 + 2*tid4];
                qa[ks][0] = lo.x; qa[ks][1] = hi.x; qa[ks][2] = lo.y; qa[ks][3] = hi.y;
            }
        }

        // ---- S = Q K^T (log2-scaled) ----
        float sfrag[16][4];
        #pragma unroll
        for (int nt = 0; nt < 16; nt++) {
            sfrag[nt][0]=0.f; sfrag[nt][1]=0.f; sfrag[nt][2]=0.f; sfrag[nt][3]=0.f;
            int krow = (nt*8 + g) * QS;
            #pragma unroll
            for (int ks = 0; ks < 8; ks++) {
                uint2 bb = *(const uint2*)&Kc[krow + ks*8 + 2*tid4];
                uint32_t bf[2] = {bb.x, bb.y};
                mma_hmma(sfrag[nt], qa[ks], bf);
            }
        }

        // ---- online softmax (base-2) ----
        float tm0 = sfrag[0][0], tm1 = sfrag[0][2];
        #pragma unroll
        for (int nt = 0; nt < 16; nt++) {
            tm0 = fmaxf(tm0, fmaxf(sfrag[nt][0], sfrag[nt][1]));
            tm1 = fmaxf(tm1, fmaxf(sfrag[nt][2], sfrag[nt][3]));
        }
        tm0 = fmaxf(tm0, __shfl_xor_sync(0xffffffffu, tm0, 1));
        tm0 = fmaxf(tm0, __shfl_xor_sync(0xffffffffu, tm0, 2));
        tm1 = fmaxf(tm1, __shfl_xor_sync(0xffffffffu, tm1, 1));
        tm1 = fmaxf(tm1, __shfl_xor_sync(0xffffffffu, tm1, 2));
        float mn0 = fmaxf(m0, tm0), mn1 = fmaxf(m1, tm1);
        float al0 = ex2(m0 - mn0), al1 = ex2(m1 - mn1);
        m0 = mn0; m1 = mn1;
        float sum0 = 0.f, sum1 = 0.f;
        #pragma unroll
        for (int nt = 0; nt < 16; nt++) {
            sfrag[nt][0] = ex2(sfrag[nt][0] - mn0);
            sfrag[nt][1] = ex2(sfrag[nt][1] - mn0);
            sfrag[nt][2] = ex2(sfrag[nt][2] - mn1);
            sfrag[nt][3] = ex2(sfrag[nt][3] - mn1);
            sum0 += sfrag[nt][0] + sfrag[nt][1];
            sum1 += sfrag[nt][2] + sfrag[nt][3];
        }
        sum0 += __shfl_xor_sync(0xffffffffu, sum0, 1);
        sum0 += __shfl_xor_sync(0xffffffffu, sum0, 2);
        sum1 += __shfl_xor_sync(0xffffffffu, sum1, 1);
        sum1 += __shfl_xor_sync(0xffffffffu, sum1, 2);
        l0 = l0*al0 + sum0;
        l1 = l1*al1 + sum1;

        #pragma unroll
        for (int dt = 0; dt < 8; dt++) {
            ofrag[dt][0] *= al0; ofrag[dt][1] *= al0;
            ofrag[dt][2] *= al1; ofrag[dt][3] *= al1;
        }

        // ---- O += P @ V (pair-packed V, conflict-free LDS.64 B-frags) ----
        #pragma unroll
        for (int ks = 0; ks < 16; ks++) {
            uint32_t p0 = f2tf(sfrag[ks][0]);
            uint32_t p1 = f2tf(sfrag[ks][1]);
            uint32_t p2 = f2tf(sfrag[ks][2]);
            uint32_t p3 = f2tf(sfrag[ks][3]);
            uint32_t x0 = __shfl_sync(0xffffffffu, p0, src0);
            uint32_t y0 = __shfl_sync(0xffffffffu, p1, src0);
            uint32_t x2 = __shfl_sync(0xffffffffu, p0, src1);
            uint32_t y2 = __shfl_sync(0xffffffffu, p1, src1);
            uint32_t x1 = __shfl_sync(0xffffffffu, p2, src0);
            uint32_t y1 = __shfl_sync(0xffffffffu, p3, src0);
            uint32_t x3 = __shfl_sync(0xffffffffu, p2, src1);
            uint32_t y3 = __shfl_sync(0xffffffffu, p3, src1);
            uint32_t af[4];
            af[0] = oddl ? y0 : x0;
            af[1] = oddl ? y1 : x1;
            af[2] = oddl ? y2 : x2;
            af[3] = oddl ? y3 : x3;
            const int vbase = (ks*4 + tid4)*VS;
            #pragma unroll
            for (int dt = 0; dt < 8; dt++) {
                uint2 vv = *(const uint2*)&Vc[vbase + (dt*8 + g)*2];
                uint32_t vb[2] = {vv.x, vv.y};
                mma_hmma(ofrag[dt], af, vb);
            }
        }
        __syncthreads();
    }

    // normalize + store pcol-packed tf32
    float inv0 = 1.0f / l0, inv1 = 1.0f / l1;
    int r0 = b*NQ + q0 + w*16 + g;
    uint32_t* AOu = g_AO;
    #pragma unroll
    for (int dt = 0; dt < 8; dt++) {
        int col = dt*8 + 2*tid4;
        int c0 = pcol(col), c1 = pcol(col + 1);
        size_t ro0 = (size_t)r0*II + h*DD;
        size_t ro1 = (size_t)(r0 + 8)*II + h*DD;
        AOu[ro0 + c0] = f2tf(ofrag[dt][0]*inv0);
        AOu[ro0 + c1] = f2tf(ofrag[dt][1]*inv0);
        AOu[ro1 + c0] = f2tf(ofrag[dt][2]*inv1);
        AOu[ro1 + c1] = f2tf(ofrag[dt][3]*inv1);
    }
}

// ============================================================================
// launch
// ============================================================================
extern "C" void kernel_launch(void* const* d_in, const int* in_sizes, int n_in,
                              void* d_out, int out_size)
{
    const float* x   = (const float*)d_in[0];
    const float* ctx = (const float*)d_in[1];
    const float* Wq  = (const float*)d_in[2];
    const float* Wk  = (const float*)d_in[3];
    const float* Wv  = (const float*)d_in[4];
    const float* Wo  = (const float*)d_in[5];
    const float* bo  = (const float*)d_in[6];
    float* out = (float*)d_out;

    uint32_t *xp, *cp, *Wqp, *Wkp, *Wvp, *Wop;
    cudaGetSymbolAddress((void**)&xp,  g_xp);
    cudaGetSymbolAddress((void**)&cp,  g_cp);
    cudaGetSymbolAddress((void**)&Wqp, g_Wqp);
    cudaGetSymbolAddress((void**)&Wkp, g_Wkp);
    cudaGetSymbolAddress((void**)&Wvp, g_Wvp);
    cudaGetSymbolAddress((void**)&Wop, g_Wop);

    // prep
    pack_a<<<(B_*NQ*CQ/4 + 255)/256, 256>>>((const float4*)x,   xp, B_*NQ*CQ/4);
    pack_a<<<(B_*NKV*CK/4 + 255)/256, 256>>>((const float4*)ctx, cp, B_*NKV*CK/4);
    pack_b<<<dim3(II/128, CQ/2), 128>>>(Wq, Wqp, II);
    pack_b<<<dim3(II/128, CK/2), 128>>>(Wk, Wkp, II);
    pack_b<<<dim3(II/128, CK/2), 128>>>(Wv, Wvp, II);
    pack_b<<<dim3(CQ/128, II/2), 128>>>(Wo, Wop, CQ);

    // projections
    cudaFuncSetAttribute(gemm_proj, cudaFuncAttributeMaxDynamicSharedMemorySize, GEMM_SMEM);
    gemm_proj<<<dim3(II/128, (B_*NQ)/128, 3), 256, GEMM_SMEM>>>();

    // attention
    cudaFuncSetAttribute(attn_tf32, cudaFuncAttributeMaxDynamicSharedMemorySize, ATT_SMEM);
    attn_tf32<<<dim3(NQ/128, B_*HH), 256, ATT_SMEM>>>();

    // output projection + bias
    cudaFuncSetAttribute(gemm_out, cudaFuncAttributeMaxDynamicSharedMemorySize, GEMM_SMEM);
    gemm_out<<<dim3(CQ/128, (B_*NQ)/128), 256, GEMM_SMEM>>>(bo, out);
}

// round 12
// speedup vs baseline: 1.2124x; 1.0943x over previous
#include <cuda_runtime.h>
#include <math.h>
#include <stdint.h>

// ---------------- problem constants ----------------
#define B_   2
#define NQ   2048
#define NKV  2048
#define CQ   1024
#define CK   768
#define HH   8
#define DD   64
#define II   (HH*DD)          // 512
#define SCALE 0.125f
#define LOG2E 1.4426950408889634f

// ---------------- scratch (all tf32 bit patterns) ----------------
__device__ uint32_t g_xp [B_*NQ *CQ];    // pcol-packed A
__device__ uint32_t g_cp [B_*NKV*CK];
__device__ uint32_t g_Wqp[CQ*II];        // (k,k+4) pair-row packed B
__device__ uint32_t g_Wkp[CK*II];
__device__ uint32_t g_Wvp[CK*II];
__device__ uint32_t g_Wop[II*CQ];
__device__ uint32_t g_Q [B_*NQ *II];     // pcol-packed, *SCALE*LOG2E
__device__ uint32_t g_K [B_*NKV*II];     // pcol-packed
__device__ uint32_t g_V [B_*NKV*II];     // (kv,kv+1) pair-row packed: [R/2][II][2]
__device__ uint32_t g_AO[B_*NQ *II];     // pcol-packed

// ---------------- helpers ----------------
__device__ __forceinline__ uint32_t f2tf(float f) {
    uint32_t u;
    asm("cvt.rna.tf32.f32 %0, %1;" : "=r"(u) : "f"(f));
    return u;
}
__device__ __forceinline__ float ex2(float x) {
    float y;
    asm("ex2.approx.ftz.f32 %0, %1;" : "=f"(y) : "f"(x));
    return y;
}
__device__ __forceinline__ void mma_hmma(float c[4], const uint32_t a[4], const uint32_t b[2]) {
    asm("mma.sync.aligned.m16n8k8.row.col.f32.tf32.tf32.f32 "
        "{%0,%1,%2,%3},{%4,%5,%6,%7},{%8,%9},{%0,%1,%2,%3};"
        : "+f"(c[0]), "+f"(c[1]), "+f"(c[2]), "+f"(c[3])
        : "r"(a[0]), "r"(a[1]), "r"(a[2]), "r"(a[3]), "r"(b[0]), "r"(b[1]));
}
__device__ __forceinline__ void cp16(void* sptr, const void* gptr) {
    uint32_t sa = (uint32_t)__cvta_generic_to_shared(sptr);
    asm volatile("cp.async.cg.shared.global [%0], [%1], 16;" :: "r"(sa), "l"(gptr));
}
#define CP_COMMIT() asm volatile("cp.async.commit_group;")

__device__ __forceinline__ int pcol(int c) {
    return (c & ~7) | ((c & 3) << 1) | ((c & 7) >> 2);
}

// ============================================================================
// fused prep kernel: all activation + weight packs in one launch
// ============================================================================
__device__ __forceinline__ void pack_a_elem(const float4* __restrict__ in,
                                            uint32_t* __restrict__ out, int i) {
    float4 v = in[i];
    int base = i * 4;
    int grp  = base & ~7;
    int off  = (base & 4) ? 1 : 0;
    out[grp + off + 0] = f2tf(v.x);
    out[grp + off + 2] = f2tf(v.y);
    out[grp + off + 4] = f2tf(v.z);
    out[grp + off + 6] = f2tf(v.w);
}
__device__ __forceinline__ void pack_b_elem(const float* __restrict__ in,
                                            uint32_t* __restrict__ out, int N, int i) {
    int kk = i / N;      // N is a power of two
    int n  = i - kk * N;
    int s  = kk >> 3;
    int pr = kk & 7;
    int k0 = s * 16 + ((pr >> 2) << 3) + (pr & 3);
    uint2 v = make_uint2(f2tf(in[(size_t)k0 * N + n]),
                         f2tf(in[(size_t)(k0 + 4) * N + n]));
    *(uint2*)&out[(size_t)i * 2] = v;
}

#define NB_X   4096   // (B_*NQ*CQ/4)/256
#define NB_C   3072   // (B_*NKV*CK/4)/256
#define NB_WQ  1024   // (CQ/2*II)/256
#define NB_WK  768
#define NB_WV  768
#define NB_WO  1024   // (II/2*CQ)/256
#define NB_ALL (NB_X+NB_C+NB_WQ+NB_WK+NB_WV+NB_WO)   // 10752

__global__ __launch_bounds__(256) void pack_all(const float4* __restrict__ x4,
                                                const float4* __restrict__ c4,
                                                const float* __restrict__ Wq,
                                                const float* __restrict__ Wk,
                                                const float* __restrict__ Wv,
                                                const float* __restrict__ Wo) {
    int bid = blockIdx.x;
    int tid = threadIdx.x;
    if (bid < NB_X) {
        pack_a_elem(x4, g_xp, bid * 256 + tid);
    } else if (bid < NB_X + NB_C) {
        pack_a_elem(c4, g_cp, (bid - NB_X) * 256 + tid);
    } else if (bid < NB_X + NB_C + NB_WQ) {
        pack_b_elem(Wq, g_Wqp, II, (bid - NB_X - NB_C) * 256 + tid);
    } else if (bid < NB_X + NB_C + NB_WQ + NB_WK) {
        pack_b_elem(Wk, g_Wkp, II, (bid - NB_X - NB_C - NB_WQ) * 256 + tid);
    } else if (bid < NB_X + NB_C + NB_WQ + NB_WK + NB_WV) {
        pack_b_elem(Wv, g_Wvp, II, (bid - NB_X - NB_C - NB_WQ - NB_WK) * 256 + tid);
    } else {
        pack_b_elem(Wo, g_Wop, CQ, (bid - NB_X - NB_C - NB_WQ - NB_WK - NB_WV) * 256 + tid);
    }
}

// ============================================================================
// TF32 GEMM (cp.async-fed, 3-stage). CTA 128x128, BK=16, 8 warps.
// mode: 0=Q (tf32, pcol, *SCALE*LOG2E)  1=K (tf32, pcol)
//       2=V (tf32, (kv,kv+1) pair-row packed)  3=f32 out + bias
// ============================================================================
#define AS 24
#define BSs 264
#define STG_A (128*AS)
#define STG_B (8*BSs)
#define STG_W (STG_A + STG_B)
#define GEMM_SMEM (3*STG_W*4)   // 62208 B

__device__ __forceinline__ void gemm_body(const uint32_t* __restrict__ Ag,
                                          const uint32_t* __restrict__ Bp,
                                          const float* __restrict__ bias,
                                          void* __restrict__ Cv,
                                          int K, int Nn, int mode,
                                          uint32_t* sm)
{
    const int t    = threadIdx.x;
    const int lane = t & 31;
    const int w    = t >> 5;
    const int wrow = w >> 2;
    const int wcol = w & 3;
    const int g    = lane >> 2;
    const int tid4 = lane & 3;
    const int bm = blockIdx.y * 128;
    const int bn = blockIdx.x * 128;
    const int NCH = K >> 4;

    auto load = [&](int ch, int st) {
        uint32_t* ab = sm + st * STG_W;
        uint32_t* bb = ab + STG_A;
        const uint32_t* Asrc = Ag + (size_t)bm * K + ch * 16;
        const uint32_t* Bsrc = Bp + ((size_t)(ch * 8) * Nn + bn) * 2;
        #pragma unroll
        for (int j = 0; j < 2; j++) {
            int idx = t + j * 256;
            int r = idx >> 2, ck = idx & 3;
            cp16(&ab[r * AS + ck * 4], Asrc + (size_t)r * K + ck * 4);
        }
        #pragma unroll
        for (int j = 0; j < 2; j++) {
            int idx = t + j * 256;
            int pr = idx >> 6, nc = idx & 63;
            cp16(&bb[pr * BSs + nc * 4], Bsrc + ((size_t)pr * Nn + nc * 2) * 2);
        }
        CP_COMMIT();
    };

    float acc[4][4][4];
    #pragma unroll
    for (int mt = 0; mt < 4; mt++)
        #pragma unroll
        for (int nt = 0; nt < 4; nt++)
            #pragma unroll
            for (int e = 0; e < 4; e++) acc[mt][nt][e] = 0.f;

    load(0, 0);
    load(1, 1);

    for (int ch = 0; ch < NCH; ch++) {
        if (ch + 1 < NCH) asm volatile("cp.async.wait_group 1;" ::: "memory");
        else              asm volatile("cp.async.wait_group 0;" ::: "memory");
        __syncthreads();
        if (ch + 2 < NCH) load(ch + 2, (ch + 2) % 3);

        const uint32_t* Asc = sm + (ch % 3) * STG_W;
        const uint32_t* Bsc = Asc + STG_A;

        #pragma unroll
        for (int ks = 0; ks < 2; ks++) {
            uint32_t af[4][4], bf[4][2];
            #pragma unroll
            for (int mt = 0; mt < 4; mt++) {
                int r = wrow*64 + mt*16 + g;
                uint2 lo = *(const uint2*)&Asc[r*AS + ks*8 + 2*tid4];
                uint2 hi = *(const uint2*)&Asc[(r+8)*AS + ks*8 + 2*tid4];
                af[mt][0] = lo.x; af[mt][1] = hi.x; af[mt][2] = lo.y; af[mt][3] = hi.y;
            }
            #pragma unroll
            for (int nt = 0; nt < 4; nt++) {
                int cidx = wcol*32 + nt*8 + g;
                uint2 bb = *(const uint2*)&Bsc[(ks*4 + tid4)*BSs + 2*cidx];
                bf[nt][0] = bb.x; bf[nt][1] = bb.y;
            }
            #pragma unroll
            for (int mt = 0; mt < 4; mt++)
                #pragma unroll
                for (int nt = 0; nt < 4; nt++)
                    mma_hmma(acc[mt][nt], af[mt], bf[nt]);
        }
    }

    // epilogue
    #pragma unroll
    for (int mt = 0; mt < 4; mt++) {
        int row0 = bm + wrow*64 + mt*16 + g;
        #pragma unroll
        for (int nt = 0; nt < 4; nt++) {
            int col = bn + wcol*32 + nt*8 + 2*tid4;
            if (mode == 3) {
                float* C = (float*)Cv;
                float bx = bias[col], by = bias[col+1];
                *(float2*)&C[(size_t)row0 * Nn + col] =
                    make_float2(acc[mt][nt][0] + bx, acc[mt][nt][1] + by);
                *(float2*)&C[(size_t)(row0 + 8) * Nn + col] =
                    make_float2(acc[mt][nt][2] + bx, acc[mt][nt][3] + by);
            } else if (mode == 2) {
                // V: (kv, kv+1) pair-row pack. Partner row is g^1 -> shfl xor 4.
                uint32_t a0 = f2tf(acc[mt][nt][0]);
                uint32_t a1 = f2tf(acc[mt][nt][1]);
                uint32_t a2 = f2tf(acc[mt][nt][2]);
                uint32_t a3 = f2tf(acc[mt][nt][3]);
                uint32_t b0 = __shfl_xor_sync(0xffffffffu, a0, 4);
                uint32_t b1 = __shfl_xor_sync(0xffffffffu, a1, 4);
                uint32_t b2 = __shfl_xor_sync(0xffffffffu, a2, 4);
                uint32_t b3 = __shfl_xor_sync(0xffffffffu, a3, 4);
                uint32_t* C = (uint32_t*)Cv;
                if (!(g & 1)) {
                    // rows (row0, row0+1): (own0, nbr0) cols col, (own1, nbr1) col+1
                    size_t P = (size_t)(row0 >> 1);
                    *(uint4*)&C[(P * Nn + col) * 2] = make_uint4(a0, b0, a1, b1);
                } else {
                    // rows (row0+7, row0+8): nbr holds row0+7's acc[2]/[3]
                    size_t P = (size_t)((row0 + 7) >> 1);
                    *(uint4*)&C[(P * Nn + col) * 2] = make_uint4(b2, a2, b3, a3);
                }
            } else {
                const float sc = (mode == 0) ? (SCALE * LOG2E) : 1.0f;
                uint32_t* C = (uint32_t*)Cv;
                int c0 = pcol(col), c1 = pcol(col + 1);
                C[(size_t)row0 * Nn + c0]       = f2tf(acc[mt][nt][0] * sc);
                C[(size_t)row0 * Nn + c1]       = f2tf(acc[mt][nt][1] * sc);
                C[(size_t)(row0 + 8) * Nn + c0] = f2tf(acc[mt][nt][2] * sc);
                C[(size_t)(row0 + 8) * Nn + c1] = f2tf(acc[mt][nt][3] * sc);
            }
        }
    }
}

__global__ __launch_bounds__(256, 2) void gemm_proj() {
    extern __shared__ __align__(16) uint32_t sm[];
    const int z = blockIdx.z;
    const uint32_t* A  = (z == 0) ? g_xp  : g_cp;
    const uint32_t* Bp = (z == 0) ? g_Wqp : ((z == 1) ? g_Wkp : g_Wvp);
    uint32_t*       C  = (z == 0) ? g_Q   : ((z == 1) ? g_K   : g_V);
    const int       K  = (z == 0) ? CQ : CK;
    gemm_body(A, Bp, nullptr, C, K, II, z, sm);
}

__global__ __launch_bounds__(256, 2) void gemm_out(const float* __restrict__ bias,
                                                   float* __restrict__ out) {
    extern __shared__ __align__(16) uint32_t sm[];
    gemm_body(g_AO, g_Wop, bias, out, II, CQ, 3, sm);
}

// ============================================================================
// TF32 flash attention. Q pre-scaled by SCALE*LOG2E -> ex2 softmax.
// V (kv,kv+1) pair-packed: S accumulator IS the PV A-frag (no shfl transpose).
// smem: Q[128x72] + 2x K[128x72] + 2x V[64x136] = 180224 B.
// ============================================================================
#define QS 72
#define VS 136
#define ATT_T_ELEMS (128*QS)     // 9216
#define V_T_ELEMS (64*VS)        // 8704
#define ATT_SMEM ((3*ATT_T_ELEMS + 2*V_T_ELEMS)*4)   // 180224 B

__global__ __launch_bounds__(256, 1) void attn_tf32() {
    extern __shared__ __align__(16) uint32_t smu[];
    uint32_t* Qs  = smu;
    uint32_t* Kb0 = smu + ATT_T_ELEMS;
    uint32_t* Kb1 = smu + 2*ATT_T_ELEMS;
    uint32_t* Vb0 = smu + 3*ATT_T_ELEMS;
    uint32_t* Vb1 = Vb0 + V_T_ELEMS;

    const uint32_t* Qg = g_Q;
    const uint32_t* Kg = g_K;
    const uint32_t* Vg = g_V;

    const int t    = threadIdx.x;
    const int lane = t & 31;
    const int w    = t >> 5;
    const int g    = lane >> 2;
    const int tid4 = lane & 3;

    const int bh = blockIdx.y;
    const int b  = bh >> 3;
    const int h  = bh & 7;
    const int q0 = blockIdx.x * 128;

    // Q tile
    #pragma unroll
    for (int j = 0; j < 8; j++) {
        int idx = t + j*256;
        int row = idx >> 4;
        int d   = (idx & 15) * 4;
        cp16(&Qs[row*QS + d], &Qg[(size_t)(b*NQ + q0 + row)*II + h*DD + d]);
    }
    // K/V tile 0
    {
        size_t Pb = ((size_t)(b*NKV)) >> 1;
        #pragma unroll
        for (int j = 0; j < 8; j++) {
            int idx = t + j*256;
            int row = idx >> 4;
            int d   = (idx & 15) * 4;
            cp16(&Kb0[row*QS + d], &Kg[(size_t)(b*NKV + row)*II + h*DD + d]);
            int pr = idx >> 5;
            int cq = idx & 31;
            cp16(&Vb0[pr*VS + cq*4], &Vg[((Pb + pr)*II + h*DD)*2 + cq*4]);
        }
    }
    CP_COMMIT();

    uint32_t qa[8][4];
    float ofrag[8][4];
    #pragma unroll
    for (int dt = 0; dt < 8; dt++)
        #pragma unroll
        for (int e = 0; e < 4; e++) ofrag[dt][e] = 0.f;
    float m0 = -1e30f, m1 = -1e30f, l0 = 0.f, l1 = 0.f;

    for (int it = 0; it < NKV/128; it++) {
        const int cur = it & 1;
        uint32_t* Kc = cur ? Kb1 : Kb0;
        uint32_t* Vc = cur ? Vb1 : Vb0;

        if (it + 1 < NKV/128) {
            uint32_t* Kn = cur ? Kb0 : Kb1;
            uint32_t* Vn = cur ? Vb0 : Vb1;
            int kv0n = (it + 1) * 128;
            size_t Pb = ((size_t)(b*NKV + kv0n)) >> 1;
            #pragma unroll
            for (int j = 0; j < 8; j++) {
                int idx = t + j*256;
                int row = idx >> 4;
                int d   = (idx & 15) * 4;
                cp16(&Kn[row*QS + d], &Kg[(size_t)(b*NKV + kv0n + row)*II + h*DD + d]);
                int pr = idx >> 5;
                int cq = idx & 31;
                cp16(&Vn[pr*VS + cq*4], &Vg[((Pb + pr)*II + h*DD)*2 + cq*4]);
            }
            CP_COMMIT();
            asm volatile("cp.async.wait_group 1;" ::: "memory");
        } else {
            asm volatile("cp.async.wait_group 0;" ::: "memory");
        }
        __syncthreads();

        if (it == 0) {
            int r0 = (w*16 + g) * QS;
            int r1 = (w*16 + g + 8) * QS;
            #pragma unroll
            for (int ks = 0; ks < 8; ks++) {
                uint2 lo = *(const uint2*)&Qs[r0 + ks*8 + 2*tid4];
                uint2 hi = *(const uint2*)&Qs[r1 + ks*8 + 2*tid4];
                qa[ks][0] = lo.x; qa[ks][1] = hi.x; qa[ks][2] = lo.y; qa[ks][3] = hi.y;
            }
        }

        // ---- S = Q K^T (log2-scaled) ----
        float sfrag[16][4];
        #pragma unroll
        for (int nt = 0; nt < 16; nt++) {
            sfrag[nt][0]=0.f; sfrag[nt][1]=0.f; sfrag[nt][2]=0.f; sfrag[nt][3]=0.f;
            int krow = (nt*8 + g) * QS;
            #pragma unroll
            for (int ks = 0; ks < 8; ks++) {
                uint2 bb = *(const uint2*)&Kc[krow + ks*8 + 2*tid4];
                uint32_t bf[2] = {bb.x, bb.y};
                mma_hmma(sfrag[nt], qa[ks], bf);
            }
        }

        // ---- online softmax (base-2) ----
        float tm0 = sfrag[0][0], tm1 = sfrag[0][2];
        #pragma unroll
        for (int nt = 0; nt < 16; nt++) {
            tm0 = fmaxf(tm0, fmaxf(sfrag[nt][0], sfrag[nt][1]));
            tm1 = fmaxf(tm1, fmaxf(sfrag[nt][2], sfrag[nt][3]));
        }
        tm0 = fmaxf(tm0, __shfl_xor_sync(0xffffffffu, tm0, 1));
        tm0 = fmaxf(tm0, __shfl_xor_sync(0xffffffffu, tm0, 2));
        tm1 = fmaxf(tm1, __shfl_xor_sync(0xffffffffu, tm1, 1));
        tm1 = fmaxf(tm1, __shfl_xor_sync(0xffffffffu, tm1, 2));
        float mn0 = fmaxf(m0, tm0), mn1 = fmaxf(m1, tm1);
        float al0 = ex2(m0 - mn0), al1 = ex2(m1 - mn1);
        m0 = mn0; m1 = mn1;
        float sum0 = 0.f, sum1 = 0.f;
        #pragma unroll
        for (int nt = 0; nt < 16; nt++) {
            sfrag[nt][0] = ex2(sfrag[nt][0] - mn0);
            sfrag[nt][1] = ex2(sfrag[nt][1] - mn0);
            sfrag[nt][2] = ex2(sfrag[nt][2] - mn1);
            sfrag[nt][3] = ex2(sfrag[nt][3] - mn1);
            sum0 += sfrag[nt][0] + sfrag[nt][1];
            sum1 += sfrag[nt][2] + sfrag[nt][3];
        }
        sum0 += __shfl_xor_sync(0xffffffffu, sum0, 1);
        sum0 += __shfl_xor_sync(0xffffffffu, sum0, 2);
        sum1 += __shfl_xor_sync(0xffffffffu, sum1, 1);
        sum1 += __shfl_xor_sync(0xffffffffu, sum1, 2);
        l0 = l0*al0 + sum0;
        l1 = l1*al1 + sum1;

        #pragma unroll
        for (int dt = 0; dt < 8; dt++) {
            ofrag[dt][0] *= al0; ofrag[dt][1] *= al0;
            ofrag[dt][2] *= al1; ofrag[dt][3] *= al1;
        }

        // ---- O += P @ V : S accumulator IS the A-frag (V rows (kv,kv+1)-paired)
        // A-frag slots: a0=(row g, k=t4)=P[col 2t4]=s0; a1=(g+8,t4)=s2;
        //               a2=(g, t4+4)=P[col 2t4+1]=s1;   a3=s3.
        #pragma unroll
        for (int ks = 0; ks < 16; ks++) {
            uint32_t af[4];
            af[0] = f2tf(sfrag[ks][0]);
            af[1] = f2tf(sfrag[ks][2]);
            af[2] = f2tf(sfrag[ks][1]);
            af[3] = f2tf(sfrag[ks][3]);
            const int vbase = (ks*4 + tid4)*VS;
            #pragma unroll
            for (int dt = 0; dt < 8; dt++) {
                uint2 vv = *(const uint2*)&Vc[vbase + (dt*8 + g)*2];
                uint32_t vb[2] = {vv.x, vv.y};
                mma_hmma(ofrag[dt], af, vb);
            }
        }
        __syncthreads();
    }

    // normalize + store pcol-packed tf32
    float inv0 = 1.0f / l0, inv1 = 1.0f / l1;
    int r0 = b*NQ + q0 + w*16 + g;
    uint32_t* AOu = g_AO;
    #pragma unroll
    for (int dt = 0; dt < 8; dt++) {
        int col = dt*8 + 2*tid4;
        int c0 = pcol(col), c1 = pcol(col + 1);
        size_t ro0 = (size_t)r0*II + h*DD;
        size_t ro1 = (size_t)(r0 + 8)*II + h*DD;
        AOu[ro0 + c0] = f2tf(ofrag[dt][0]*inv0);
        AOu[ro0 + c1] = f2tf(ofrag[dt][1]*inv0);
        AOu[ro1 + c0] = f2tf(ofrag[dt][2]*inv1);
        AOu[ro1 + c1] = f2tf(ofrag[dt][3]*inv1);
    }
}

// ============================================================================
// launch
// ============================================================================
extern "C" void kernel_launch(void* const* d_in, const int* in_sizes, int n_in,
                              void* d_out, int out_size)
{
    const float* x   = (const float*)d_in[0];
    const float* ctx = (const float*)d_in[1];
    const float* Wq  = (const float*)d_in[2];
    const float* Wk  = (const float*)d_in[3];
    const float* Wv  = (const float*)d_in[4];
    const float* Wo  = (const float*)d_in[5];
    const float* bo  = (const float*)d_in[6];
    float* out = (float*)d_out;

    // prep (single fused launch)
    pack_all<<<NB_ALL, 256>>>((const float4*)x, (const float4*)ctx, Wq, Wk, Wv, Wo);

    // projections
    cudaFuncSetAttribute(gemm_proj, cudaFuncAttributeMaxDynamicSharedMemorySize, GEMM_SMEM);
    gemm_proj<<<dim3(II/128, (B_*NQ)/128, 3), 256, GEMM_SMEM>>>();

    // attention
    cudaFuncSetAttribute(attn_tf32, cudaFuncAttributeMaxDynamicSharedMemorySize, ATT_SMEM);
    attn_tf32<<<dim3(NQ/128, B_*HH), 256, ATT_SMEM>>>();

    // output projection + bias
    cudaFuncSetAttribute(gemm_out, cudaFuncAttributeMaxDynamicSharedMemorySize, GEMM_SMEM);
    gemm_out<<<dim3(CQ/128, (B_*NQ)/128), 256, GEMM_SMEM>>>(bo, out);
}

// round 16
// speedup vs baseline: 1.2287x; 1.0134x over previous
#include <cuda_runtime.h>
#include <math.h>
#include <stdint.h>

// ---------------- problem constants ----------------
#define B_   2
#define NQ   2048
#define NKV  2048
#define CQ   1024
#define CK   768
#define HH   8
#define DD   64
#define II   (HH*DD)          // 512
#define SCALE 0.125f
#define LOG2E 1.4426950408889634f

// ---------------- scratch (all tf32 bit patterns) ----------------
__device__ uint32_t g_xp [B_*NQ *CQ];    // pcol-packed A
__device__ uint32_t g_cp [B_*NKV*CK];
__device__ uint32_t g_Wqp[CQ*II];        // (k,k+4) pair-row packed B
__device__ uint32_t g_Wkp[CK*II];
__device__ uint32_t g_Wvp[CK*II];
__device__ uint32_t g_Wop[II*CQ];
__device__ uint32_t g_Q [B_*NQ *II];     // pcol-packed, *SCALE*LOG2E
__device__ uint32_t g_K [B_*NKV*II];     // pcol-packed
__device__ uint32_t g_V [B_*NKV*II];     // (kv,kv+1) pair-row packed: [R/2][II][2]
__device__ uint32_t g_AO[B_*NQ *II];     // pcol-packed

// ---------------- helpers ----------------
__device__ __forceinline__ uint32_t f2tf(float f) {
    uint32_t u;
    asm("cvt.rna.tf32.f32 %0, %1;" : "=r"(u) : "f"(f));
    return u;
}
__device__ __forceinline__ float ex2(float x) {
    float y;
    asm("ex2.approx.ftz.f32 %0, %1;" : "=f"(y) : "f"(x));
    return y;
}
__device__ __forceinline__ void mma_hmma(float c[4], const uint32_t a[4], const uint32_t b[2]) {
    asm("mma.sync.aligned.m16n8k8.row.col.f32.tf32.tf32.f32 "
        "{%0,%1,%2,%3},{%4,%5,%6,%7},{%8,%9},{%0,%1,%2,%3};"
        : "+f"(c[0]), "+f"(c[1]), "+f"(c[2]), "+f"(c[3])
        : "r"(a[0]), "r"(a[1]), "r"(a[2]), "r"(a[3]), "r"(b[0]), "r"(b[1]));
}
__device__ __forceinline__ void cp16(void* sptr, const void* gptr) {
    uint32_t sa = (uint32_t)__cvta_generic_to_shared(sptr);
    asm volatile("cp.async.cg.shared.global [%0], [%1], 16;" :: "r"(sa), "l"(gptr));
}
#define CP_COMMIT() asm volatile("cp.async.commit_group;")

__device__ __forceinline__ int pcol(int c) {
    return (c & ~7) | ((c & 3) << 1) | ((c & 7) >> 2);
}

// ============================================================================
// fused prep kernel
// ============================================================================
__device__ __forceinline__ void pack_a_elem(const float4* __restrict__ in,
                                            uint32_t* __restrict__ out, int i) {
    float4 v = in[i];
    int base = i * 4;
    int grp  = base & ~7;
    int off  = (base & 4) ? 1 : 0;
    out[grp + off + 0] = f2tf(v.x);
    out[grp + off + 2] = f2tf(v.y);
    out[grp + off + 4] = f2tf(v.z);
    out[grp + off + 6] = f2tf(v.w);
}
__device__ __forceinline__ void pack_b_elem(const float* __restrict__ in,
                                            uint32_t* __restrict__ out, int N, int i) {
    int kk = i / N;
    int n  = i - kk * N;
    int s  = kk >> 3;
    int pr = kk & 7;
    int k0 = s * 16 + ((pr >> 2) << 3) + (pr & 3);
    uint2 v = make_uint2(f2tf(in[(size_t)k0 * N + n]),
                         f2tf(in[(size_t)(k0 + 4) * N + n]));
    *(uint2*)&out[(size_t)i * 2] = v;
}

#define NB_X   4096
#define NB_C   3072
#define NB_WQ  1024
#define NB_WK  768
#define NB_WV  768
#define NB_WO  1024
#define NB_ALL (NB_X+NB_C+NB_WQ+NB_WK+NB_WV+NB_WO)   // 10752

__global__ __launch_bounds__(256) void pack_all(const float4* __restrict__ x4,
                                                const float4* __restrict__ c4,
                                                const float* __restrict__ Wq,
                                                const float* __restrict__ Wk,
                                                const float* __restrict__ Wv,
                                                const float* __restrict__ Wo) {
    int bid = blockIdx.x;
    int tid = threadIdx.x;
    if (bid < NB_X) {
        pack_a_elem(x4, g_xp, bid * 256 + tid);
    } else if (bid < NB_X + NB_C) {
        pack_a_elem(c4, g_cp, (bid - NB_X) * 256 + tid);
    } else if (bid < NB_X + NB_C + NB_WQ) {
        pack_b_elem(Wq, g_Wqp, II, (bid - NB_X - NB_C) * 256 + tid);
    } else if (bid < NB_X + NB_C + NB_WQ + NB_WK) {
        pack_b_elem(Wk, g_Wkp, II, (bid - NB_X - NB_C - NB_WQ) * 256 + tid);
    } else if (bid < NB_X + NB_C + NB_WQ + NB_WK + NB_WV) {
        pack_b_elem(Wv, g_Wvp, II, (bid - NB_X - NB_C - NB_WQ - NB_WK) * 256 + tid);
    } else {
        pack_b_elem(Wo, g_Wop, CQ, (bid - NB_X - NB_C - NB_WQ - NB_WK - NB_WV) * 256 + tid);
    }
}

// ============================================================================
// TF32 GEMM (cp.async-fed, 3-stage). CTA 128x128, BK=16, 8 warps.
// ============================================================================
#define AS 24
#define BSs 264
#define STG_A (128*AS)
#define STG_B (8*BSs)
#define STG_W (STG_A + STG_B)
#define GEMM_SMEM (3*STG_W*4)   // 62208 B

__device__ __forceinline__ void gemm_body(const uint32_t* __restrict__ Ag,
                                          const uint32_t* __restrict__ Bp,
                                          const float* __restrict__ bias,
                                          void* __restrict__ Cv,
                                          int K, int Nn, int mode,
                                          uint32_t* sm)
{
    const int t    = threadIdx.x;
    const int lane = t & 31;
    const int w    = t >> 5;
    const int wrow = w >> 2;
    const int wcol = w & 3;
    const int g    = lane >> 2;
    const int tid4 = lane & 3;
    const int bm = blockIdx.y * 128;
    const int bn = blockIdx.x * 128;
    const int NCH = K >> 4;

    auto load = [&](int ch, int st) {
        uint32_t* ab = sm + st * STG_W;
        uint32_t* bb = ab + STG_A;
        const uint32_t* Asrc = Ag + (size_t)bm * K + ch * 16;
        const uint32_t* Bsrc = Bp + ((size_t)(ch * 8) * Nn + bn) * 2;
        #pragma unroll
        for (int j = 0; j < 2; j++) {
            int idx = t + j * 256;
            int r = idx >> 2, ck = idx & 3;
            cp16(&ab[r * AS + ck * 4], Asrc + (size_t)r * K + ck * 4);
        }
        #pragma unroll
        for (int j = 0; j < 2; j++) {
            int idx = t + j * 256;
            int pr = idx >> 6, nc = idx & 63;
            cp16(&bb[pr * BSs + nc * 4], Bsrc + ((size_t)pr * Nn + nc * 2) * 2);
        }
        CP_COMMIT();
    };

    float acc[4][4][4];
    #pragma unroll
    for (int mt = 0; mt < 4; mt++)
        #pragma unroll
        for (int nt = 0; nt < 4; nt++)
            #pragma unroll
            for (int e = 0; e < 4; e++) acc[mt][nt][e] = 0.f;

    load(0, 0);
    load(1, 1);

    for (int ch = 0; ch < NCH; ch++) {
        if (ch + 1 < NCH) asm volatile("cp.async.wait_group 1;" ::: "memory");
        else              asm volatile("cp.async.wait_group 0;" ::: "memory");
        __syncthreads();
        if (ch + 2 < NCH) load(ch + 2, (ch + 2) % 3);

        const uint32_t* Asc = sm + (ch % 3) * STG_W;
        const uint32_t* Bsc = Asc + STG_A;

        #pragma unroll
        for (int ks = 0; ks < 2; ks++) {
            uint32_t af[4][4], bf[4][2];
            #pragma unroll
            for (int mt = 0; mt < 4; mt++) {
                int r = wrow*64 + mt*16 + g;
                uint2 lo = *(const uint2*)&Asc[r*AS + ks*8 + 2*tid4];
                uint2 hi = *(const uint2*)&Asc[(r+8)*AS + ks*8 + 2*tid4];
                af[mt][0] = lo.x; af[mt][1] = hi.x; af[mt][2] = lo.y; af[mt][3] = hi.y;
            }
            #pragma unroll
            for (int nt = 0; nt < 4; nt++) {
                int cidx = wcol*32 + nt*8 + g;
                uint2 bb = *(const uint2*)&Bsc[(ks*4 + tid4)*BSs + 2*cidx];
                bf[nt][0] = bb.x; bf[nt][1] = bb.y;
            }
            #pragma unroll
            for (int mt = 0; mt < 4; mt++)
                #pragma unroll
                for (int nt = 0; nt < 4; nt++)
                    mma_hmma(acc[mt][nt], af[mt], bf[nt]);
        }
    }

    // epilogue
    #pragma unroll
    for (int mt = 0; mt < 4; mt++) {
        int row0 = bm + wrow*64 + mt*16 + g;
        #pragma unroll
        for (int nt = 0; nt < 4; nt++) {
            int col = bn + wcol*32 + nt*8 + 2*tid4;
            if (mode == 3) {
                float* C = (float*)Cv;
                float bx = bias[col], by = bias[col+1];
                *(float2*)&C[(size_t)row0 * Nn + col] =
                    make_float2(acc[mt][nt][0] + bx, acc[mt][nt][1] + by);
                *(float2*)&C[(size_t)(row0 + 8) * Nn + col] =
                    make_float2(acc[mt][nt][2] + bx, acc[mt][nt][3] + by);
            } else if (mode == 2) {
                uint32_t a0 = f2tf(acc[mt][nt][0]);
                uint32_t a1 = f2tf(acc[mt][nt][1]);
                uint32_t a2 = f2tf(acc[mt][nt][2]);
                uint32_t a3 = f2tf(acc[mt][nt][3]);
                uint32_t b0 = __shfl_xor_sync(0xffffffffu, a0, 4);
                uint32_t b1 = __shfl_xor_sync(0xffffffffu, a1, 4);
                uint32_t b2 = __shfl_xor_sync(0xffffffffu, a2, 4);
                uint32_t b3 = __shfl_xor_sync(0xffffffffu, a3, 4);
                uint32_t* C = (uint32_t*)Cv;
                if (!(g & 1)) {
                    size_t P = (size_t)(row0 >> 1);
                    *(uint4*)&C[(P * Nn + col) * 2] = make_uint4(a0, b0, a1, b1);
                } else {
                    size_t P = (size_t)((row0 + 7) >> 1);
                    *(uint4*)&C[(P * Nn + col) * 2] = make_uint4(b2, a2, b3, a3);
                }
            } else {
                const float sc = (mode == 0) ? (SCALE * LOG2E) : 1.0f;
                uint32_t* C = (uint32_t*)Cv;
                int c0 = pcol(col), c1 = pcol(col + 1);
                C[(size_t)row0 * Nn + c0]       = f2tf(acc[mt][nt][0] * sc);
                C[(size_t)row0 * Nn + c1]       = f2tf(acc[mt][nt][1] * sc);
                C[(size_t)(row0 + 8) * Nn + c0] = f2tf(acc[mt][nt][2] * sc);
                C[(size_t)(row0 + 8) * Nn + c1] = f2tf(acc[mt][nt][3] * sc);
            }
        }
    }
}

__global__ __launch_bounds__(256, 2) void gemm_proj() {
    extern __shared__ __align__(16) uint32_t sm[];
    const int z = blockIdx.z;
    const uint32_t* A  = (z == 0) ? g_xp  : g_cp;
    const uint32_t* Bp = (z == 0) ? g_Wqp : ((z == 1) ? g_Wkp : g_Wvp);
    uint32_t*       C  = (z == 0) ? g_Q   : ((z == 1) ? g_K   : g_V);
    const int       K  = (z == 0) ? CQ : CK;
    gemm_body(A, Bp, nullptr, C, K, II, z, sm);
}

__global__ __launch_bounds__(256, 2) void gemm_out(const float* __restrict__ bias,
                                                   float* __restrict__ out) {
    extern __shared__ __align__(16) uint32_t sm[];
    gemm_body(g_AO, g_Wop, bias, out, II, CQ, 3, sm);
}

// ============================================================================
// TF32 flash attention, 2 CTAs/SM. KV tile = 64 (32 iterations).
// Q frags reloaded from smem per ks (frees 32 regs -> fits 128-reg cap).
// smem: Q[128x72] + 2x K[64x72] + 2x V[32x136] = 108544 B.
// ============================================================================
#define QS 72
#define VS 136
#define Q_ELEMS (128*QS)         // 9216
#define K_T_ELEMS (64*QS)        // 4608
#define V_T_ELEMS (32*VS)        // 4352
#define ATT_SMEM ((Q_ELEMS + 2*K_T_ELEMS + 2*V_T_ELEMS)*4)   // 108544 B
#define NIT (NKV/64)             // 32

__global__ __launch_bounds__(256, 2) void attn_tf32() {
    extern __shared__ __align__(16) uint32_t smu[];
    uint32_t* Qs  = smu;
    uint32_t* Kb0 = smu + Q_ELEMS;
    uint32_t* Kb1 = Kb0 + K_T_ELEMS;
    uint32_t* Vb0 = Kb1 + K_T_ELEMS;
    uint32_t* Vb1 = Vb0 + V_T_ELEMS;

    const uint32_t* Qg = g_Q;
    const uint32_t* Kg = g_K;
    const uint32_t* Vg = g_V;

    const int t    = threadIdx.x;
    const int lane = t & 31;
    const int w    = t >> 5;
    const int g    = lane >> 2;
    const int tid4 = lane & 3;

    const int bh = blockIdx.y;
    const int b  = bh >> 3;
    const int h  = bh & 7;
    const int q0 = blockIdx.x * 128;

    // Q tile (128 x 64)
    #pragma unroll
    for (int j = 0; j < 8; j++) {
        int idx = t + j*256;
        int row = idx >> 4;
        int d   = (idx & 15) * 4;
        cp16(&Qs[row*QS + d], &Qg[(size_t)(b*NQ + q0 + row)*II + h*DD + d]);
    }
    // K/V tile 0 (64 kv rows)
    {
        size_t Pb = ((size_t)(b*NKV)) >> 1;
        #pragma unroll
        for (int j = 0; j < 4; j++) {
            int idx = t + j*256;
            int row = idx >> 4;          // 0..63
            int d   = (idx & 15) * 4;
            cp16(&Kb0[row*QS + d], &Kg[(size_t)(b*NKV + row)*II + h*DD + d]);
            int pr = idx >> 5;           // 0..31
            int cq = idx & 31;
            cp16(&Vb0[pr*VS + cq*4], &Vg[((Pb + pr)*II + h*DD)*2 + cq*4]);
        }
    }
    CP_COMMIT();

    float ofrag[8][4];
    #pragma unroll
    for (int dt = 0; dt < 8; dt++)
        #pragma unroll
        for (int e = 0; e < 4; e++) ofrag[dt][e] = 0.f;
    float m0 = -1e30f, m1 = -1e30f, l0 = 0.f, l1 = 0.f;

    const int qr0 = (w*16 + g) * QS;
    const int qr1 = (w*16 + g + 8) * QS;

    for (int it = 0; it < NIT; it++) {
        const int cur = it & 1;
        uint32_t* Kc = cur ? Kb1 : Kb0;
        uint32_t* Vc = cur ? Vb1 : Vb0;

        if (it + 1 < NIT) {
            uint32_t* Kn = cur ? Kb0 : Kb1;
            uint32_t* Vn = cur ? Vb0 : Vb1;
            int kv0n = (it + 1) * 64;
            size_t Pb = ((size_t)(b*NKV + kv0n)) >> 1;
            #pragma unroll
            for (int j = 0; j < 4; j++) {
                int idx = t + j*256;
                int row = idx >> 4;
                int d   = (idx & 15) * 4;
                cp16(&Kn[row*QS + d], &Kg[(size_t)(b*NKV + kv0n + row)*II + h*DD + d]);
                int pr = idx >> 5;
                int cq = idx & 31;
                cp16(&Vn[pr*VS + cq*4], &Vg[((Pb + pr)*II + h*DD)*2 + cq*4]);
            }
            CP_COMMIT();
            asm volatile("cp.async.wait_group 1;" ::: "memory");
        } else {
            asm volatile("cp.async.wait_group 0;" ::: "memory");
        }
        __syncthreads();

        // ---- S = Q K^T (log2-scaled): 8 nt x 8 ks, Q frags from smem ----
        float sfrag[8][4];
        #pragma unroll
        for (int nt = 0; nt < 8; nt++) {
            sfrag[nt][0]=0.f; sfrag[nt][1]=0.f; sfrag[nt][2]=0.f; sfrag[nt][3]=0.f;
        }
        #pragma unroll
        for (int ks = 0; ks < 8; ks++) {
            uint32_t qf[4];
            {
                uint2 lo = *(const uint2*)&Qs[qr0 + ks*8 + 2*tid4];
                uint2 hi = *(const uint2*)&Qs[qr1 + ks*8 + 2*tid4];
                qf[0] = lo.x; qf[1] = hi.x; qf[2] = lo.y; qf[3] = hi.y;
            }
            #pragma unroll
            for (int nt = 0; nt < 8; nt++) {
                uint2 bb = *(const uint2*)&Kc[(nt*8 + g)*QS + ks*8 + 2*tid4];
                uint32_t bf[2] = {bb.x, bb.y};
                mma_hmma(sfrag[nt], qf, bf);
            }
        }

        // ---- online softmax (base-2) ----
        float tm0 = sfrag[0][0], tm1 = sfrag[0][2];
        #pragma unroll
        for (int nt = 0; nt < 8; nt++) {
            tm0 = fmaxf(tm0, fmaxf(sfrag[nt][0], sfrag[nt][1]));
            tm1 = fmaxf(tm1, fmaxf(sfrag[nt][2], sfrag[nt][3]));
        }
        tm0 = fmaxf(tm0, __shfl_xor_sync(0xffffffffu, tm0, 1));
        tm0 = fmaxf(tm0, __shfl_xor_sync(0xffffffffu, tm0, 2));
        tm1 = fmaxf(tm1, __shfl_xor_sync(0xffffffffu, tm1, 1));
        tm1 = fmaxf(tm1, __shfl_xor_sync(0xffffffffu, tm1, 2));
        float mn0 = fmaxf(m0, tm0), mn1 = fmaxf(m1, tm1);
        float al0 = ex2(m0 - mn0), al1 = ex2(m1 - mn1);
        m0 = mn0; m1 = mn1;
        float sum0 = 0.f, sum1 = 0.f;
        #pragma unroll
        for (int nt = 0; nt < 8; nt++) {
            sfrag[nt][0] = ex2(sfrag[nt][0] - mn0);
            sfrag[nt][1] = ex2(sfrag[nt][1] - mn0);
            sfrag[nt][2] = ex2(sfrag[nt][2] - mn1);
            sfrag[nt][3] = ex2(sfrag[nt][3] - mn1);
            sum0 += sfrag[nt][0] + sfrag[nt][1];
            sum1 += sfrag[nt][2] + sfrag[nt][3];
        }
        sum0 += __shfl_xor_sync(0xffffffffu, sum0, 1);
        sum0 += __shfl_xor_sync(0xffffffffu, sum0, 2);
        sum1 += __shfl_xor_sync(0xffffffffu, sum1, 1);
        sum1 += __shfl_xor_sync(0xffffffffu, sum1, 2);
        l0 = l0*al0 + sum0;
        l1 = l1*al1 + sum1;

        #pragma unroll
        for (int dt = 0; dt < 8; dt++) {
            ofrag[dt][0] *= al0; ofrag[dt][1] *= al0;
            ofrag[dt][2] *= al1; ofrag[dt][3] *= al1;
        }

        // ---- O += P @ V : S accumulator IS the A-frag ----
        #pragma unroll
        for (int ks = 0; ks < 8; ks++) {
            uint32_t af[4];
            af[0] = f2tf(sfrag[ks][0]);
            af[1] = f2tf(sfrag[ks][2]);
            af[2] = f2tf(sfrag[ks][1]);
            af[3] = f2tf(sfrag[ks][3]);
            const int vbase = (ks*4 + tid4)*VS;
            #pragma unroll
            for (int dt = 0; dt < 8; dt++) {
                uint2 vv = *(const uint2*)&Vc[vbase + (dt*8 + g)*2];
                uint32_t vb[2] = {vv.x, vv.y};
                mma_hmma(ofrag[dt], af, vb);
            }
        }
        __syncthreads();
    }

    // normalize + store pcol-packed tf32
    float inv0 = 1.0f / l0, inv1 = 1.0f / l1;
    int r0 = b*NQ + q0 + w*16 + g;
    uint32_t* AOu = g_AO;
    #pragma unroll
    for (int dt = 0; dt < 8; dt++) {
        int col = dt*8 + 2*tid4;
        int c0 = pcol(col), c1 = pcol(col + 1);
        size_t ro0 = (size_t)r0*II + h*DD;
        size_t ro1 = (size_t)(r0 + 8)*II + h*DD;
        AOu[ro0 + c0] = f2tf(ofrag[dt][0]*inv0);
        AOu[ro0 + c1] = f2tf(ofrag[dt][1]*inv0);
        AOu[ro1 + c0] = f2tf(ofrag[dt][2]*inv1);
        AOu[ro1 + c1] = f2tf(ofrag[dt][3]*inv1);
    }
}

// ============================================================================
// launch
// ============================================================================
extern "C" void kernel_launch(void* const* d_in, const int* in_sizes, int n_in,
                              void* d_out, int out_size)
{
    const float* x   = (const float*)d_in[0];
    const float* ctx = (const float*)d_in[1];
    const float* Wq  = (const float*)d_in[2];
    const float* Wk  = (const float*)d_in[3];
    const float* Wv  = (const float*)d_in[4];
    const float* Wo  = (const float*)d_in[5];
    const float* bo  = (const float*)d_in[6];
    float* out = (float*)d_out;

    // prep (single fused launch)
    pack_all<<<NB_ALL, 256>>>((const float4*)x, (const float4*)ctx, Wq, Wk, Wv, Wo);

    // projections
    cudaFuncSetAttribute(gemm_proj, cudaFuncAttributeMaxDynamicSharedMemorySize, GEMM_SMEM);
    gemm_proj<<<dim3(II/128, (B_*NQ)/128, 3), 256, GEMM_SMEM>>>();

    // attention (2 CTAs/SM, single wave: 256 CTAs <= 296 slots)
    cudaFuncSetAttribute(attn_tf32, cudaFuncAttributeMaxDynamicSharedMemorySize, ATT_SMEM);
    attn_tf32<<<dim3(NQ/128, B_*HH), 256, ATT_SMEM>>>();

    // output projection + bias
    cudaFuncSetAttribute(gemm_out, cudaFuncAttributeMaxDynamicSharedMemorySize, GEMM_SMEM);
    gemm_out<<<dim3(CQ/128, (B_*NQ)/128), 256, GEMM_SMEM>>>(bo, out);
}